// round 16
// baseline (speedup 1.0000x reference)
#include <cuda_runtime.h>
#include <cstdint>

#define N_NODES 50000
#define N_EDGES 600000
#define D_K     128
#define D_H1    128
#define D_H2    64

#define SCAN_NB ((N_NODES + 255) / 256)                // 196

// ---------------- scratch (device globals: no allocation allowed) ----------
// g_deg is zero at module load and re-zeroed by k_scanBC each run (invariant).
__device__ int   g_deg     [N_NODES];
__device__ float g_dinv    [N_NODES];
__device__ int   g_bsum    [SCAN_NB];
__device__ int   g_rowstart[N_NODES + 1];
__device__ int   g_cursor  [N_NODES];
__device__ int   g_csr_src [N_EDGES];
__device__ __align__(16) float g_t1  [N_NODES * D_H1];   // x @ W1 (raw)
__device__ __align__(16) float g_agg1[N_NODES * D_H1];   // aggregated layer-1
__device__ __align__(16) float g_t2  [N_NODES * D_H2];   // (relu(agg1+b1) @ W2) * dinv

__device__ __forceinline__ int clampi(int v) {
    return min(max(v, 0), N_NODES - 1);
}

// ---------------- tensor-core GEMM (3xTF32) helpers --------------------------
__device__ __forceinline__ unsigned f2tf32(float x) {
    unsigned r;
    asm("cvt.rna.tf32.f32 %0, %1;" : "=r"(r) : "f"(x));
    return r;
}

__device__ __forceinline__ void mma_tf32(float* d, const unsigned* a, const unsigned* b) {
    asm volatile(
        "mma.sync.aligned.m16n8k8.row.col.f32.tf32.tf32.f32 "
        "{%0,%1,%2,%3}, {%4,%5,%6,%7}, {%8,%9}, {%0,%1,%2,%3};"
        : "+f"(d[0]), "+f"(d[1]), "+f"(d[2]), "+f"(d[3])
        : "r"(a[0]), "r"(a[1]), "r"(a[2]), "r"(a[3]), "r"(b[0]), "r"(b[1]));
}

__device__ __forceinline__ void cp16(uint32_t dst, const void* src, int sz) {
    asm volatile("cp.async.cg.shared.global [%0], [%1], 16, %2;"
                 :: "r"(dst), "l"(src), "r"(sz));
}

// BM=128 x BN=64 block tile, 8 warps (2x4), warp tile 64x16 (MT=4, NT=2).
// Double-buffered smem, cp.async staging of chunk k+1 overlaps compute of k.
template<int NOUT, bool IN_TRANS, bool PRESCALE>
__device__ __forceinline__ void gemm_tc_body(const float* __restrict__ A,
                                             const float* __restrict__ W,
                                             const float* __restrict__ b_in,
                                             float* __restrict__ T,
                                             int bx, int by)
{
    constexpr int BM = 128, BN = 64;
    constexpr int KC = 16, NK = D_K / KC;     // 8 chunks
    constexpr int AP = KC + 4;                // 20
    constexpr int WP = BN + 8;                // 72
    constexpr int MT = 4, NT = 2;

    __shared__ float As[2][BM][AP];           // 20.0 KB
    __shared__ float Ws[2][KC][WP];           //  9.2 KB

    const int tid   = threadIdx.x;
    const int wid   = tid >> 5;
    const int lane  = tid & 31;
    const int wm    = wid & 1;
    const int wn    = wid >> 1;
    const int group = lane >> 2;              // 0..7
    const int tig   = lane & 3;               // 0..3
    const int row0  = bx * BM;
    const int n0    = by * BN;
    const int mbase = wm * 64;
    const int nbase = wn * 16;

    float acc[MT][NT][4];
#pragma unroll
    for (int im = 0; im < MT; im++)
#pragma unroll
        for (int in = 0; in < NT; in++)
#pragma unroll
            for (int e = 0; e < 4; e++) acc[im][in][e] = 0.f;

    auto stage = [&](int buf, int kc) {
#pragma unroll
        for (int q = 0; q < 2; q++) {
            int f  = tid + q * 256;
            int r  = f >> 2;
            int k4 = f & 3;
            int gr = row0 + r;
            const float* src = &A[(size_t)clampi(gr) * D_K + kc + k4 * 4];
            uint32_t dst = (uint32_t)__cvta_generic_to_shared(&As[buf][r][k4 * 4]);
            cp16(dst, src, gr < N_NODES ? 16 : 0);
        }
        {
            int kk = tid >> 4;
            int n4 = tid & 15;
            const float* src = &W[(size_t)(kc + kk) * NOUT + n0 + n4 * 4];
            uint32_t dst = (uint32_t)__cvta_generic_to_shared(&Ws[buf][kk][n4 * 4]);
            cp16(dst, src, 16);
        }
        asm volatile("cp.async.commit_group;" ::: "memory");
    };

    stage(0, 0);
    int buf = 0;

#pragma unroll
    for (int kci = 0; kci < NK; kci++) {
        asm volatile("cp.async.wait_group 0;" ::: "memory");
        __syncthreads();
        if (kci + 1 < NK) stage(buf ^ 1, (kci + 1) * KC);

#pragma unroll
        for (int ks = 0; ks < KC / 8; ks++) {
            float bias0 = 0.f, bias1 = 0.f;
            if constexpr (IN_TRANS) {
                int k0 = ks * 8 + tig;
                bias0 = b_in[kci * KC + k0];
                bias1 = b_in[kci * KC + k0 + 4];
            }
            unsigned ah[MT][4], al[MT][4];
#pragma unroll
            for (int im = 0; im < MT; im++) {
#pragma unroll
                for (int e = 0; e < 4; e++) {
                    int r = mbase + im * 16 + group + (e & 1) * 8;
                    int k = ks * 8 + tig + (e >> 1) * 4;
                    float a = As[buf][r][k];
                    if constexpr (IN_TRANS)
                        a = fmaxf(a + ((e >> 1) ? bias1 : bias0), 0.f);
                    unsigned h = f2tf32(a);
                    ah[im][e] = h;
                    al[im][e] = f2tf32(a - __uint_as_float(h));
                }
            }
#pragma unroll
            for (int in = 0; in < NT; in++) {
                unsigned bh[2], bl[2];
#pragma unroll
                for (int e = 0; e < 2; e++) {
                    int k = ks * 8 + tig + e * 4;
                    int n = nbase + in * 8 + group;
                    float b = Ws[buf][k][n];
                    unsigned h = f2tf32(b);
                    bh[e] = h;
                    bl[e] = f2tf32(b - __uint_as_float(h));
                }
#pragma unroll
                for (int im = 0; im < MT; im++) {
                    mma_tf32(acc[im][in], ah[im], bh);
                    mma_tf32(acc[im][in], ah[im], bl);
                    mma_tf32(acc[im][in], al[im], bh);
                }
            }
        }
        buf ^= 1;
    }

#pragma unroll
    for (int im = 0; im < MT; im++) {
#pragma unroll
        for (int half = 0; half < 2; half++) {
            int r = row0 + mbase + im * 16 + group + half * 8;
            if (r >= N_NODES) continue;
            float dv = PRESCALE ? g_dinv[r] : 1.0f;
#pragma unroll
            for (int in = 0; in < NT; in++) {
                float2 t;
                t.x = acc[im][in][half * 2 + 0] * dv;
                t.y = acc[im][in][half * 2 + 1] * dv;
                *(float2*)&T[(size_t)r * NOUT + n0 + nbase + in * 8 + 2 * tig] = t;
            }
        }
    }
}

// ---------------- fused launches: gemm1 split in ROW halves -----------------
// Row split partitions A traffic (no duplication; W is tiny). Half A (rows
// [0, RSPLIT*128)) carries the degree count; half B carries the CSR fill.
// Deps: count -> scans -> fill; gemm1 rows depend only on inputs.
#define G1_ROWS    ((N_NODES + 127) / 128)             // 391 row tiles
#define RSPLIT     (G1_ROWS / 2)                       // 195
#define G1A_TILES  (RSPLIT * 2)                        // 390 (x2 col tiles)
#define G1B_TILES  ((G1_ROWS - RSPLIT) * 2)            // 392
#define EDG_BLOCKS ((N_EDGES + 255) / 256)             // 2344

__global__ void __launch_bounds__(256, 2)
k_g1a_count(const float* __restrict__ x, const float* __restrict__ W1,
            const int* __restrict__ ei)
{
    int b = blockIdx.x;
    if (b < G1A_TILES) {
        gemm_tc_body<D_H1, false, false>(x, W1, nullptr, g_t1, b >> 1, b & 1);
    } else {
        int e = (b - G1A_TILES) * 256 + threadIdx.x;
        if (e < N_EDGES) atomicAdd(&g_deg[clampi(ei[N_EDGES + e])], 1);
    }
}

__global__ void __launch_bounds__(256, 2)
k_g1b_fill(const float* __restrict__ x, const float* __restrict__ W1,
           const int* __restrict__ ei)
{
    int b = blockIdx.x;
    if (b < G1B_TILES) {
        gemm_tc_body<D_H1, false, false>(x, W1, nullptr, g_t1,
                                         RSPLIT + (b >> 1), b & 1);
    } else {
        int e = (b - G1B_TILES) * 256 + threadIdx.x;
        if (e < N_EDGES) {
            int src = clampi(ei[e]);
            int dst = clampi(ei[N_EDGES + e]);
            int pos = atomicAdd(&g_cursor[dst], 1);
            g_csr_src[pos] = src;
        }
    }
}

__global__ void __launch_bounds__(256, 2)
k_gemm2(const float* __restrict__ W2, const float* __restrict__ b1) {
    gemm_tc_body<D_H2, true, true>(g_agg1, W2, b1, g_t2, blockIdx.x, 0);
}

// ---------------- scan phase A: per-block sums -------------------------------
__global__ void k_scanA() {
    __shared__ int sh[256];
    int t = threadIdx.x;
    int n = blockIdx.x * 256 + t;
    sh[t] = (n < N_NODES) ? g_deg[n] : 0;
    __syncthreads();
#pragma unroll
    for (int off = 128; off; off >>= 1) {
        if (t < off) sh[t] += sh[t + off];
        __syncthreads();
    }
    if (t == 0) g_bsum[blockIdx.x] = sh[0];
}

// ---------------- scan phase B+C fused: every block re-scans block sums -----
__global__ void k_scanBC() {
    __shared__ int bs[256];
    __shared__ int sh[256];
    int t = threadIdx.x;

    bs[t] = (t < SCAN_NB) ? g_bsum[t] : 0;
    int n = blockIdx.x * 256 + t;
    int d = (n < N_NODES) ? g_deg[n] : 0;
    sh[t] = d;
    __syncthreads();

    for (int off = 1; off < 256; off <<= 1) {
        int addb = (t >= off) ? bs[t - off] : 0;
        int adds = (t >= off) ? sh[t - off] : 0;
        __syncthreads();
        bs[t] += addb;
        sh[t] += adds;
        __syncthreads();
    }

    // exclusive base of this block = inclusive-scan[bid] - own block sum
    int block_base = bs[blockIdx.x] - g_bsum[blockIdx.x];

    if (n < N_NODES) {
        int run = block_base + sh[t] - d;      // exclusive prefix
        g_rowstart[n] = run;
        g_cursor[n]   = run;
        g_dinv[n]     = rsqrtf((float)(d + 1));  // +1 self-loop
        g_deg[n]      = 0;                        // restore zero
    }
    if (blockIdx.x == 0 && t == 255)
        g_rowstart[N_NODES] = bs[255];            // total == N_EDGES
}

// ---------------- layer-1 aggregate: t1 raw, per-edge dinv[src] -------------
__global__ void k_agg1() {
    int n    = (blockIdx.x * blockDim.x + threadIdx.x) >> 5;
    int lane = threadIdx.x & 31;
    if (n >= N_NODES) return;

    int   s0 = g_rowstart[n];
    int   s1 = g_rowstart[n + 1];
    float dv = g_dinv[n];

    float4 acc = *(const float4*)&g_t1[(size_t)n * D_H1 + lane * 4];
    acc.x *= dv; acc.y *= dv; acc.z *= dv; acc.w *= dv;

    int e = s0;
    for (; e + 1 < s1; e += 2) {
        int srcA = g_csr_src[e];
        int srcB = g_csr_src[e + 1];
        float nmA = g_dinv[srcA];
        float nmB = g_dinv[srcB];
        float4 vA = *(const float4*)&g_t1[(size_t)srcA * D_H1 + lane * 4];
        float4 vB = *(const float4*)&g_t1[(size_t)srcB * D_H1 + lane * 4];
        acc.x = fmaf(vA.x, nmA, acc.x);
        acc.y = fmaf(vA.y, nmA, acc.y);
        acc.z = fmaf(vA.z, nmA, acc.z);
        acc.w = fmaf(vA.w, nmA, acc.w);
        acc.x = fmaf(vB.x, nmB, acc.x);
        acc.y = fmaf(vB.y, nmB, acc.y);
        acc.z = fmaf(vB.z, nmB, acc.z);
        acc.w = fmaf(vB.w, nmB, acc.w);
    }
    if (e < s1) {
        int src = g_csr_src[e];
        float nm = g_dinv[src];
        float4 v = *(const float4*)&g_t1[(size_t)src * D_H1 + lane * 4];
        acc.x = fmaf(v.x, nm, acc.x);
        acc.y = fmaf(v.y, nm, acc.y);
        acc.z = fmaf(v.z, nm, acc.z);
        acc.w = fmaf(v.w, nm, acc.w);
    }
    acc.x *= dv; acc.y *= dv; acc.z *= dv; acc.w *= dv;
    *(float4*)&g_agg1[(size_t)n * D_H1 + lane * 4] = acc;
}

// ---------------- layer-2 aggregate (t2 prescaled) + final GEMV -------------
__global__ void k_agg2_final(const float* __restrict__ b2,
                             const float* __restrict__ W3,
                             const float* __restrict__ b3,
                             float* __restrict__ out)
{
    int n    = (blockIdx.x * blockDim.x + threadIdx.x) >> 5;
    int lane = threadIdx.x & 31;
    if (n >= N_NODES) return;

    int   s0 = g_rowstart[n];
    int   s1 = g_rowstart[n + 1];
    float dv = g_dinv[n];

    float2 acc = *(const float2*)&g_t2[(size_t)n * D_H2 + lane * 2];

    int e = s0;
    for (; e + 1 < s1; e += 2) {
        int srcA = g_csr_src[e];
        int srcB = g_csr_src[e + 1];
        float2 vA = *(const float2*)&g_t2[(size_t)srcA * D_H2 + lane * 2];
        float2 vB = *(const float2*)&g_t2[(size_t)srcB * D_H2 + lane * 2];
        acc.x += vA.x + vB.x;
        acc.y += vA.y + vB.y;
    }
    if (e < s1) {
        int src = g_csr_src[e];
        float2 v = *(const float2*)&g_t2[(size_t)src * D_H2 + lane * 2];
        acc.x += v.x; acc.y += v.y;
    }
    acc.x *= dv; acc.y *= dv;

    float2 bb = *(const float2*)&b2[lane * 2];
    float2 w  = *(const float2*)&W3[lane * 2];
    float h0 = fmaxf(acc.x + bb.x, 0.f);
    float h1 = fmaxf(acc.y + bb.y, 0.f);
    float s  = fmaf(h0, w.x, h1 * w.y);
#pragma unroll
    for (int o = 16; o; o >>= 1) s += __shfl_xor_sync(0xffffffffu, s, o);
    if (lane == 0) out[n] = s + b3[0];
}

// ---------------- launch (single stream) ------------------------------------
extern "C" void kernel_launch(void* const* d_in, const int* in_sizes, int n_in,
                              void* d_out, int out_size)
{
    const float* x  = (const float*)d_in[0];
    const int*   ei = (const int*)d_in[1];     // int32 edge_index
    const float* W1 = (const float*)d_in[2];
    const float* b1 = (const float*)d_in[3];
    const float* W2 = (const float*)d_in[4];
    const float* b2 = (const float*)d_in[5];
    const float* W3 = (const float*)d_in[6];
    const float* b3 = (const float*)d_in[7];
    float*       out = (float*)d_out;
    (void)in_sizes; (void)n_in; (void)out_size;

    k_g1a_count <<<G1A_TILES + EDG_BLOCKS, 256>>>(x, W1, ei);   // 1: gemm1 rows A + count
    k_scanA     <<<SCAN_NB, 256>>>();                            // 2
    k_scanBC    <<<SCAN_NB, 256>>>();                            // 3
    k_g1b_fill  <<<G1B_TILES + EDG_BLOCKS, 256>>>(x, W1, ei);   // 4: gemm1 rows B + fill
    k_agg1      <<<(N_NODES * 32 + 255) / 256, 256>>>();         // 5
    k_gemm2     <<<(N_NODES + 127) / 128, 256>>>(W2, b1);        // 6
    k_agg2_final<<<(N_NODES * 32 + 255) / 256, 256>>>(b2, W3, b3, out);
}

// round 17
// speedup vs baseline: 1.0546x; 1.0546x over previous
#include <cuda_runtime.h>
#include <cstdint>

#define N_NODES 50000
#define N_EDGES 600000
#define D_K     128
#define D_H1    128
#define D_H2    64

#define SCAN_NB ((N_NODES + 255) / 256)                // 196

// ---------------- scratch (device globals: no allocation allowed) ----------
// g_deg is zero at module load and re-zeroed by k_scanBC each run (invariant).
__device__ int   g_deg     [N_NODES];
__device__ float g_dinv    [N_NODES];
__device__ int   g_bsum    [SCAN_NB];
__device__ int   g_rowstart[N_NODES + 1];
__device__ int   g_cursor  [N_NODES];
__device__ int   g_csr_src [N_EDGES];
__device__ __align__(16) float g_t1  [N_NODES * D_H1];   // x @ W1 (raw)
__device__ __align__(16) float g_agg1[N_NODES * D_H1];   // aggregated layer-1
__device__ __align__(16) float g_t2  [N_NODES * D_H2];   // (relu(agg1+b1) @ W2) * dinv

__device__ __forceinline__ int clampi(int v) {
    return min(max(v, 0), N_NODES - 1);
}

// ---------------- tensor-core GEMM (3xTF32) helpers --------------------------
__device__ __forceinline__ unsigned f2tf32(float x) {
    unsigned r;
    asm("cvt.rna.tf32.f32 %0, %1;" : "=r"(r) : "f"(x));
    return r;
}

__device__ __forceinline__ void mma_tf32(float* d, const unsigned* a, const unsigned* b) {
    asm volatile(
        "mma.sync.aligned.m16n8k8.row.col.f32.tf32.tf32.f32 "
        "{%0,%1,%2,%3}, {%4,%5,%6,%7}, {%8,%9}, {%0,%1,%2,%3};"
        : "+f"(d[0]), "+f"(d[1]), "+f"(d[2]), "+f"(d[3])
        : "r"(a[0]), "r"(a[1]), "r"(a[2]), "r"(a[3]), "r"(b[0]), "r"(b[1]));
}

__device__ __forceinline__ void cp16(uint32_t dst, const void* src, int sz) {
    asm volatile("cp.async.cg.shared.global [%0], [%1], 16, %2;"
                 :: "r"(dst), "l"(src), "r"(sz));
}

// BM=128 x BN=64 block tile, 8 warps (2x4), warp tile 64x16 (MT=4, NT=2).
// Double-buffered smem, cp.async staging of chunk k+1 overlaps compute of k.
template<int NOUT, bool IN_TRANS, bool PRESCALE>
__device__ __forceinline__ void gemm_tc_body(const float* __restrict__ A,
                                             const float* __restrict__ W,
                                             const float* __restrict__ b_in,
                                             float* __restrict__ T,
                                             int bx, int by)
{
    constexpr int BM = 128, BN = 64;
    constexpr int KC = 16, NK = D_K / KC;     // 8 chunks
    constexpr int AP = KC + 4;                // 20
    constexpr int WP = BN + 8;                // 72
    constexpr int MT = 4, NT = 2;

    __shared__ float As[2][BM][AP];           // 20.0 KB
    __shared__ float Ws[2][KC][WP];           //  9.2 KB

    const int tid   = threadIdx.x;
    const int wid   = tid >> 5;
    const int lane  = tid & 31;
    const int wm    = wid & 1;
    const int wn    = wid >> 1;
    const int group = lane >> 2;              // 0..7
    const int tig   = lane & 3;               // 0..3
    const int row0  = bx * BM;
    const int n0    = by * BN;
    const int mbase = wm * 64;
    const int nbase = wn * 16;

    float acc[MT][NT][4];
#pragma unroll
    for (int im = 0; im < MT; im++)
#pragma unroll
        for (int in = 0; in < NT; in++)
#pragma unroll
            for (int e = 0; e < 4; e++) acc[im][in][e] = 0.f;

    auto stage = [&](int buf, int kc) {
#pragma unroll
        for (int q = 0; q < 2; q++) {
            int f  = tid + q * 256;
            int r  = f >> 2;
            int k4 = f & 3;
            int gr = row0 + r;
            const float* src = &A[(size_t)clampi(gr) * D_K + kc + k4 * 4];
            uint32_t dst = (uint32_t)__cvta_generic_to_shared(&As[buf][r][k4 * 4]);
            cp16(dst, src, gr < N_NODES ? 16 : 0);
        }
        {
            int kk = tid >> 4;
            int n4 = tid & 15;
            const float* src = &W[(size_t)(kc + kk) * NOUT + n0 + n4 * 4];
            uint32_t dst = (uint32_t)__cvta_generic_to_shared(&Ws[buf][kk][n4 * 4]);
            cp16(dst, src, 16);
        }
        asm volatile("cp.async.commit_group;" ::: "memory");
    };

    stage(0, 0);
    int buf = 0;

#pragma unroll
    for (int kci = 0; kci < NK; kci++) {
        asm volatile("cp.async.wait_group 0;" ::: "memory");
        __syncthreads();
        if (kci + 1 < NK) stage(buf ^ 1, (kci + 1) * KC);

#pragma unroll
        for (int ks = 0; ks < KC / 8; ks++) {
            float bias0 = 0.f, bias1 = 0.f;
            if constexpr (IN_TRANS) {
                int k0 = ks * 8 + tig;
                bias0 = b_in[kci * KC + k0];
                bias1 = b_in[kci * KC + k0 + 4];
            }
            unsigned ah[MT][4], al[MT][4];
#pragma unroll
            for (int im = 0; im < MT; im++) {
#pragma unroll
                for (int e = 0; e < 4; e++) {
                    int r = mbase + im * 16 + group + (e & 1) * 8;
                    int k = ks * 8 + tig + (e >> 1) * 4;
                    float a = As[buf][r][k];
                    if constexpr (IN_TRANS)
                        a = fmaxf(a + ((e >> 1) ? bias1 : bias0), 0.f);
                    unsigned h = f2tf32(a);
                    ah[im][e] = h;
                    al[im][e] = f2tf32(a - __uint_as_float(h));
                }
            }
#pragma unroll
            for (int in = 0; in < NT; in++) {
                unsigned bh[2], bl[2];
#pragma unroll
                for (int e = 0; e < 2; e++) {
                    int k = ks * 8 + tig + e * 4;
                    int n = nbase + in * 8 + group;
                    float b = Ws[buf][k][n];
                    unsigned h = f2tf32(b);
                    bh[e] = h;
                    bl[e] = f2tf32(b - __uint_as_float(h));
                }
#pragma unroll
                for (int im = 0; im < MT; im++) {
                    mma_tf32(acc[im][in], ah[im], bh);
                    mma_tf32(acc[im][in], ah[im], bl);
                    mma_tf32(acc[im][in], al[im], bh);
                }
            }
        }
        buf ^= 1;
    }

#pragma unroll
    for (int im = 0; im < MT; im++) {
#pragma unroll
        for (int half = 0; half < 2; half++) {
            int r = row0 + mbase + im * 16 + group + half * 8;
            if (r >= N_NODES) continue;
            float dv = PRESCALE ? g_dinv[r] : 1.0f;
#pragma unroll
            for (int in = 0; in < NT; in++) {
                float2 t;
                t.x = acc[im][in][half * 2 + 0] * dv;
                t.y = acc[im][in][half * 2 + 1] * dv;
                *(float2*)&T[(size_t)r * NOUT + n0 + nbase + in * 8 + 2 * tig] = t;
            }
        }
    }
}

// ---------------- fused launches: gemm1 split in ROW halves -----------------
#define G1_ROWS    ((N_NODES + 127) / 128)             // 391 row tiles
#define RSPLIT     (G1_ROWS / 2)                       // 195
#define G1A_TILES  (RSPLIT * 2)                        // 390
#define G1B_TILES  ((G1_ROWS - RSPLIT) * 2)            // 392
#define EDG_BLOCKS ((N_EDGES + 255) / 256)             // 2344

__global__ void __launch_bounds__(256, 3)
k_g1a_count(const float* __restrict__ x, const float* __restrict__ W1,
            const int* __restrict__ ei)
{
    int b = blockIdx.x;
    if (b < G1A_TILES) {
        gemm_tc_body<D_H1, false, false>(x, W1, nullptr, g_t1, b >> 1, b & 1);
    } else {
        int e = (b - G1A_TILES) * 256 + threadIdx.x;
        if (e < N_EDGES) atomicAdd(&g_deg[clampi(ei[N_EDGES + e])], 1);
    }
}

__global__ void __launch_bounds__(256, 3)
k_g1b_fill(const float* __restrict__ x, const float* __restrict__ W1,
           const int* __restrict__ ei)
{
    int b = blockIdx.x;
    if (b < G1B_TILES) {
        gemm_tc_body<D_H1, false, false>(x, W1, nullptr, g_t1,
                                         RSPLIT + (b >> 1), b & 1);
    } else {
        int e = (b - G1B_TILES) * 256 + threadIdx.x;
        if (e < N_EDGES) {
            int src = clampi(ei[e]);
            int dst = clampi(ei[N_EDGES + e]);
            int pos = atomicAdd(&g_cursor[dst], 1);
            g_csr_src[pos] = src;
        }
    }
}

__global__ void __launch_bounds__(256, 3)
k_gemm2(const float* __restrict__ W2, const float* __restrict__ b1) {
    gemm_tc_body<D_H2, true, true>(g_agg1, W2, b1, g_t2, blockIdx.x, 0);
}

// ---------------- scan phase A: per-block sums -------------------------------
__global__ void k_scanA() {
    __shared__ int sh[256];
    int t = threadIdx.x;
    int n = blockIdx.x * 256 + t;
    sh[t] = (n < N_NODES) ? g_deg[n] : 0;
    __syncthreads();
#pragma unroll
    for (int off = 128; off; off >>= 1) {
        if (t < off) sh[t] += sh[t + off];
        __syncthreads();
    }
    if (t == 0) g_bsum[blockIdx.x] = sh[0];
}

// ---------------- scan phase B+C fused: every block re-scans block sums -----
__global__ void k_scanBC() {
    __shared__ int bs[256];
    __shared__ int sh[256];
    int t = threadIdx.x;

    bs[t] = (t < SCAN_NB) ? g_bsum[t] : 0;
    int n = blockIdx.x * 256 + t;
    int d = (n < N_NODES) ? g_deg[n] : 0;
    sh[t] = d;
    __syncthreads();

    for (int off = 1; off < 256; off <<= 1) {
        int addb = (t >= off) ? bs[t - off] : 0;
        int adds = (t >= off) ? sh[t - off] : 0;
        __syncthreads();
        bs[t] += addb;
        sh[t] += adds;
        __syncthreads();
    }

    int block_base = bs[blockIdx.x] - g_bsum[blockIdx.x];  // exclusive base

    if (n < N_NODES) {
        int run = block_base + sh[t] - d;      // exclusive prefix
        g_rowstart[n] = run;
        g_cursor[n]   = run;
        g_dinv[n]     = rsqrtf((float)(d + 1));  // +1 self-loop
        g_deg[n]      = 0;                        // restore zero
    }
    if (blockIdx.x == 0 && t == 255)
        g_rowstart[N_NODES] = bs[255];            // total == N_EDGES
}

// ---------------- layer-1 aggregate: t1 raw, per-edge dinv[src] -------------
__global__ void k_agg1() {
    int n    = (blockIdx.x * blockDim.x + threadIdx.x) >> 5;
    int lane = threadIdx.x & 31;
    if (n >= N_NODES) return;

    int   s0 = g_rowstart[n];
    int   s1 = g_rowstart[n + 1];
    float dv = g_dinv[n];

    float4 acc = *(const float4*)&g_t1[(size_t)n * D_H1 + lane * 4];
    acc.x *= dv; acc.y *= dv; acc.z *= dv; acc.w *= dv;

    int e = s0;
    for (; e + 1 < s1; e += 2) {
        int srcA = g_csr_src[e];
        int srcB = g_csr_src[e + 1];
        float nmA = g_dinv[srcA];
        float nmB = g_dinv[srcB];
        float4 vA = *(const float4*)&g_t1[(size_t)srcA * D_H1 + lane * 4];
        float4 vB = *(const float4*)&g_t1[(size_t)srcB * D_H1 + lane * 4];
        acc.x = fmaf(vA.x, nmA, acc.x);
        acc.y = fmaf(vA.y, nmA, acc.y);
        acc.z = fmaf(vA.z, nmA, acc.z);
        acc.w = fmaf(vA.w, nmA, acc.w);
        acc.x = fmaf(vB.x, nmB, acc.x);
        acc.y = fmaf(vB.y, nmB, acc.y);
        acc.z = fmaf(vB.z, nmB, acc.z);
        acc.w = fmaf(vB.w, nmB, acc.w);
    }
    if (e < s1) {
        int src = g_csr_src[e];
        float nm = g_dinv[src];
        float4 v = *(const float4*)&g_t1[(size_t)src * D_H1 + lane * 4];
        acc.x = fmaf(v.x, nm, acc.x);
        acc.y = fmaf(v.y, nm, acc.y);
        acc.z = fmaf(v.z, nm, acc.z);
        acc.w = fmaf(v.w, nm, acc.w);
    }
    acc.x *= dv; acc.y *= dv; acc.z *= dv; acc.w *= dv;
    *(float4*)&g_agg1[(size_t)n * D_H1 + lane * 4] = acc;
}

// ---------------- layer-2 aggregate (t2 prescaled) + final GEMV -------------
__global__ void k_agg2_final(const float* __restrict__ b2,
                             const float* __restrict__ W3,
                             const float* __restrict__ b3,
                             float* __restrict__ out)
{
    int n    = (blockIdx.x * blockDim.x + threadIdx.x) >> 5;
    int lane = threadIdx.x & 31;
    if (n >= N_NODES) return;

    int   s0 = g_rowstart[n];
    int   s1 = g_rowstart[n + 1];
    float dv = g_dinv[n];

    float2 acc = *(const float2*)&g_t2[(size_t)n * D_H2 + lane * 2];

    int e = s0;
    for (; e + 1 < s1; e += 2) {
        int srcA = g_csr_src[e];
        int srcB = g_csr_src[e + 1];
        float2 vA = *(const float2*)&g_t2[(size_t)srcA * D_H2 + lane * 2];
        float2 vB = *(const float2*)&g_t2[(size_t)srcB * D_H2 + lane * 2];
        acc.x += vA.x + vB.x;
        acc.y += vA.y + vB.y;
    }
    if (e < s1) {
        int src = g_csr_src[e];
        float2 v = *(const float2*)&g_t2[(size_t)src * D_H2 + lane * 2];
        acc.x += v.x; acc.y += v.y;
    }
    acc.x *= dv; acc.y *= dv;

    float2 bb = *(const float2*)&b2[lane * 2];
    float2 w  = *(const float2*)&W3[lane * 2];
    float h0 = fmaxf(acc.x + bb.x, 0.f);
    float h1 = fmaxf(acc.y + bb.y, 0.f);
    float s  = fmaf(h0, w.x, h1 * w.y);
#pragma unroll
    for (int o = 16; o; o >>= 1) s += __shfl_xor_sync(0xffffffffu, s, o);
    if (lane == 0) out[n] = s + b3[0];
}

// ---------------- launch (single stream) ------------------------------------
extern "C" void kernel_launch(void* const* d_in, const int* in_sizes, int n_in,
                              void* d_out, int out_size)
{
    const float* x  = (const float*)d_in[0];
    const int*   ei = (const int*)d_in[1];     // int32 edge_index
    const float* W1 = (const float*)d_in[2];
    const float* b1 = (const float*)d_in[3];
    const float* W2 = (const float*)d_in[4];
    const float* b2 = (const float*)d_in[5];
    const float* W3 = (const float*)d_in[6];
    const float* b3 = (const float*)d_in[7];
    float*       out = (float*)d_out;
    (void)in_sizes; (void)n_in; (void)out_size;

    k_g1a_count <<<G1A_TILES + EDG_BLOCKS, 256>>>(x, W1, ei);   // 1
    k_scanA     <<<SCAN_NB, 256>>>();                            // 2
    k_scanBC    <<<SCAN_NB, 256>>>();                            // 3
    k_g1b_fill  <<<G1B_TILES + EDG_BLOCKS, 256>>>(x, W1, ei);   // 4 (profiled)
    k_agg1      <<<(N_NODES * 32 + 255) / 256, 256>>>();         // 5
    k_gemm2     <<<(N_NODES + 127) / 128, 256>>>(W2, b1);        // 6
    k_agg2_final<<<(N_NODES * 32 + 255) / 256, 256>>>(b2, W3, b3, out);
}